// round 9
// baseline (speedup 1.0000x reference)
#include <cuda_runtime.h>
#include <cuda_fp16.h>
#include <cstdint>
#include <cstddef>

#define XROW 10242
#define BROWS 16384
#define KT 32
#define NT 321                     // ceil(10242/32)
#define KPAD (NT * KT)             // 10272
#define NW 112                     // 96 emb cols + 3 count cols + pad
#define MT 128
#define ASTRIDE 80                 // bytes per A smem row (32 halves + pad) -> conflict-free frags
#define BSTRIDE 80
#define A_BYTES (128 * ASTRIDE)    // 10240
#define B_BYTES (112 * BSTRIDE)    // 8960
#define CSTRIDE 113                // odd float stride -> conflict-free row reads
#define SMEM_DYN (128 * CSTRIDE * 4 + 1024)   // 58880; tile buffers (38400) fit inside

__device__ __half g_Wh[NW * KPAD]; // packed block-structured fp16 weights (2.3 MB)

// ---------------- helpers ----------------
__device__ __forceinline__ uint32_t smem_u32(const void* p) {
    uint32_t a;
    asm("{ .reg .u64 t; cvta.to.shared.u64 t, %1; cvt.u32.u64 %0, t; }" : "=r"(a) : "l"(p));
    return a;
}
__device__ __forceinline__ uint32_t lds32(uint32_t a) {
    uint32_t v;
    asm volatile("ld.shared.b32 %0, [%1];" : "=r"(v) : "r"(a));
    return v;
}
__device__ __forceinline__ void cp16(uint32_t dst, const void* src) {
    asm volatile("cp.async.cg.shared.global [%0], [%1], 16;" :: "r"(dst), "l"(src) : "memory");
}
__device__ __forceinline__ void mma16816(float* c, const uint32_t* a, uint32_t b0, uint32_t b1) {
    asm volatile(
        "mma.sync.aligned.m16n8k16.row.col.f32.f16.f16.f32 "
        "{%0,%1,%2,%3}, {%4,%5,%6,%7}, {%8,%9}, {%0,%1,%2,%3};"
        : "+f"(c[0]), "+f"(c[1]), "+f"(c[2]), "+f"(c[3])
        : "r"(a[0]), "r"(a[1]), "r"(a[2]), "r"(a[3]), "r"(b0), "r"(b1));
}

// ---------------- prep: pack W into [NW][KPAD] fp16 ----------------
// k=0: rate idx (zero row); k in [1,26): genre; [26,2212): director; [2212,10242): actor;
// [10242,KPAD): zero pad. Rows 96/97/98 are count indicator rows (1.0) per segment.
__global__ void prep_w_kernel(const float* __restrict__ Wg,
                              const float* __restrict__ Wd,
                              const float* __restrict__ Wa) {
    int idx = blockIdx.x * blockDim.x + threadIdx.x;
    if (idx >= NW * KPAD) return;
    int n = idx / KPAD;
    int k = idx - n * KPAD;
    float v = 0.0f;
    if (k >= 1 && k < 26) {
        if (n < 32)       v = Wg[n * 25 + (k - 1)];
        else if (n == 96) v = 1.0f;
    } else if (k >= 26 && k < 2212) {
        if (n >= 32 && n < 64) v = Wd[(n - 32) * 2186 + (k - 26)];
        else if (n == 97)      v = 1.0f;
    } else if (k >= 2212 && k < 10242) {
        if (n >= 64 && n < 96) v = Wa[(n - 64) * 8030 + (k - 2212)];
        else if (n == 98)      v = 1.0f;
    }
    g_Wh[idx] = __float2half_rn(v);
}

// ---------------- main kernel ----------------
__global__ void __launch_bounds__(256, 1)
mli_main_kernel(const int* __restrict__ x,
                const float* __restrict__ rate_table,
                float* __restrict__ out) {
    extern __shared__ char smem_raw[];
    const int tid  = threadIdx.x;
    const int wid  = tid >> 5;
    const int lane = tid & 31;
    const int gid  = lane >> 2;
    const int tid4 = lane & 3;
    const int wm   = wid >> 1;         // 0..3 : M warp tile
    const int wn   = wid & 1;          // 0..1 : N warp tile
    const int m_base = blockIdx.x * MT;

    uint32_t sbase = smem_u32(smem_raw);
    uint32_t tb = (sbase + 1023u) & ~1023u;
    const uint32_t Abuf[2] = { tb, tb + A_BYTES };
    const uint32_t Bbuf[2] = { tb + 2u * A_BYTES, tb + 2u * A_BYTES + B_BYTES };

    // A staging: thread handles half a row (16 ints)
    const int arow = tid >> 1;
    const int ah   = tid & 1;
    const int* xrow = x + (size_t)(m_base + arow) * XROW + ah * 16;
    const uint32_t a_dst_off = (uint32_t)(arow * ASTRIDE + ah * 32);

    int2 areg[8];

    auto load_a = [&](int k0, bool tail) {
        if (!tail) {
#pragma unroll
            for (int i = 0; i < 8; ++i) areg[i] = *(const int2*)(xrow + k0 + i * 2);
        } else {
#pragma unroll
            for (int i = 0; i < 8; ++i) {
                int base = k0 + ah * 16 + i * 2;
                int v0 = (base     < XROW) ? xrow[k0 + i * 2]     : 0;
                int v1 = (base + 1 < XROW) ? xrow[k0 + i * 2 + 1] : 0;
                areg[i] = make_int2(v0, v1);
            }
        }
    };
    auto sts_a = [&](int buf) {
        uint32_t d = Abuf[buf] + a_dst_off;
        uint32_t h[8];
#pragma unroll
        for (int i = 0; i < 8; ++i) {
            __half2 hh = __floats2half2_rn((float)areg[i].x, (float)areg[i].y);
            h[i] = *reinterpret_cast<uint32_t*>(&hh);
        }
        asm volatile("st.shared.v4.b32 [%0], {%1,%2,%3,%4};"
                     :: "r"(d), "r"(h[0]), "r"(h[1]), "r"(h[2]), "r"(h[3]) : "memory");
        asm volatile("st.shared.v4.b32 [%0], {%1,%2,%3,%4};"
                     :: "r"(d + 16), "r"(h[4]), "r"(h[5]), "r"(h[6]), "r"(h[7]) : "memory");
    };
    auto cp_b = [&](int k0, int buf) {
#pragma unroll
        for (int i = 0; i < 2; ++i) {
            int c = tid + i * 256;
            if (c < 448) {                       // 112 rows x 4 chunks of 16B
                int n = c >> 2, ch = c & 3;
                cp16(Bbuf[buf] + (uint32_t)(n * BSTRIDE + ch * 16),
                     g_Wh + (size_t)n * KPAD + k0 + ch * 8);
            }
        }
    };

    float acc[2][7][4];
#pragma unroll
    for (int mi = 0; mi < 2; ++mi)
#pragma unroll
        for (int j = 0; j < 7; ++j)
#pragma unroll
            for (int q = 0; q < 4; ++q) acc[mi][j][q] = 0.0f;

    // prologue: stage tile 0
    load_a(0, false);
    cp_b(0, 0);
    asm volatile("cp.async.commit_group;" ::: "memory");
    sts_a(0);

    for (int t = 0; t < NT; ++t) {
        const int buf = t & 1;
        if (t + 1 < NT) {
            load_a((t + 1) * KT, (t + 1) == NT - 1);
            cp_b((t + 1) * KT, buf ^ 1);
            asm volatile("cp.async.commit_group;" ::: "memory");
            asm volatile("cp.async.wait_group 1;" ::: "memory");
        } else {
            asm volatile("cp.async.wait_group 0;" ::: "memory");
        }
        __syncthreads();

        const uint32_t Ab = Abuf[buf], Bb = Bbuf[buf];
#pragma unroll
        for (int ks = 0; ks < 2; ++ks) {
            uint32_t afr[2][4];
#pragma unroll
            for (int mi = 0; mi < 2; ++mi) {
                uint32_t ab = Ab + (uint32_t)((wm * 32 + mi * 16 + gid) * ASTRIDE
                                              + ks * 32 + tid4 * 4);
                afr[mi][0] = lds32(ab);
                afr[mi][1] = lds32(ab + 8 * ASTRIDE);
                afr[mi][2] = lds32(ab + 16);
                afr[mi][3] = lds32(ab + 8 * ASTRIDE + 16);
            }
#pragma unroll
            for (int j = 0; j < 7; ++j) {
                uint32_t bb = Bb + (uint32_t)((wn * 56 + j * 8 + gid) * BSTRIDE
                                              + ks * 32 + tid4 * 4);
                uint32_t b0 = lds32(bb);
                uint32_t b1 = lds32(bb + 16);
                mma16816(acc[0][j], afr[0], b0, b1);
                mma16816(acc[1][j], afr[1], b0, b1);
            }
        }
        __syncthreads();
        if (t + 1 < NT) sts_a(buf ^ 1);
    }

    // ---------------- epilogue ----------------
    // dump accumulators to SMEM (reuses tile buffers; all mma done after trailing sync)
    float* Cs = (float*)(smem_raw + (tb - sbase));
#pragma unroll
    for (int mi = 0; mi < 2; ++mi) {
        int r0 = wm * 32 + mi * 16 + gid;
#pragma unroll
        for (int j = 0; j < 7; ++j) {
            int c0 = wn * 56 + j * 8 + tid4 * 2;
            Cs[r0 * CSTRIDE + c0]           = acc[mi][j][0];
            Cs[r0 * CSTRIDE + c0 + 1]       = acc[mi][j][1];
            Cs[(r0 + 8) * CSTRIDE + c0]     = acc[mi][j][2];
            Cs[(r0 + 8) * CSTRIDE + c0 + 1] = acc[mi][j][3];
        }
    }
    __syncthreads();

    if (tid < 128) {
        const int rg = m_base + tid;
        const float* cr = Cs + tid * CSTRIDE;
        float invg = 1.0f / cr[96];
        float invd = 1.0f / cr[97];
        float inva = 1.0f / cr[98];

        int ridx = x[(size_t)rg * XROW];
        const float4* rt = (const float4*)(rate_table + ridx * 32);
        float4 rv[8];
        float sq = 0.0f;
#pragma unroll
        for (int i = 0; i < 8; ++i) {
            rv[i] = rt[i];
            sq += rv[i].x * rv[i].x + rv[i].y * rv[i].y + rv[i].z * rv[i].z + rv[i].w * rv[i].w;
        }
        float norm = sqrtf(sq);
        float scale = (norm > 1.0f) ? (1.0f / (norm + 1e-7f)) : 1.0f;

        float4* o = (float4*)(out + (size_t)rg * 128);
#pragma unroll
        for (int i = 0; i < 8; ++i)
            o[i] = make_float4(rv[i].x * scale, rv[i].y * scale,
                               rv[i].z * scale, rv[i].w * scale);
#pragma unroll
        for (int i = 0; i < 8; ++i)
            o[8 + i] = make_float4(cr[4 * i + 0] * invg, cr[4 * i + 1] * invg,
                                   cr[4 * i + 2] * invg, cr[4 * i + 3] * invg);
#pragma unroll
        for (int i = 0; i < 8; ++i)
            o[16 + i] = make_float4(cr[32 + 4 * i + 0] * invd, cr[32 + 4 * i + 1] * invd,
                                    cr[32 + 4 * i + 2] * invd, cr[32 + 4 * i + 3] * invd);
#pragma unroll
        for (int i = 0; i < 8; ++i)
            o[24 + i] = make_float4(cr[64 + 4 * i + 0] * inva, cr[64 + 4 * i + 1] * inva,
                                    cr[64 + 4 * i + 2] * inva, cr[64 + 4 * i + 3] * inva);
    }
}

// ---------------- launch ----------------
extern "C" void kernel_launch(void* const* d_in, const int* in_sizes, int n_in,
                              void* d_out, int out_size) {
    (void)in_sizes; (void)n_in; (void)out_size;
    const int*   x    = (const int*)d_in[0];
    const float* rate = (const float*)d_in[1];
    const float* Wg   = (const float*)d_in[2];
    const float* Wd   = (const float*)d_in[3];
    const float* Wa   = (const float*)d_in[4];
    float*       out  = (float*)d_out;

    prep_w_kernel<<<(NW * KPAD + 255) / 256, 256>>>(Wg, Wd, Wa);

    cudaFuncSetAttribute(mli_main_kernel,
                         cudaFuncAttributeMaxDynamicSharedMemorySize, SMEM_DYN);
    mli_main_kernel<<<BROWS / MT, 256, SMEM_DYN>>>(x, rate, out);
}

// round 11
// speedup vs baseline: 1.0354x; 1.0354x over previous
#include <cuda_runtime.h>
#include <cuda_fp16.h>
#include <cstdint>
#include <cstddef>

#define XROW 10242
#define BROWS 16384
#define KT 32
#define NT 321                     // ceil(10242/32)
#define KPAD (NT * KT)             // 10272
#define NW 112                     // 96 emb cols + 3 count cols + pad
#define MT 128
#define ASTRIDE 80                 // bytes per A smem row (32 halves + pad) -> conflict-free frags
#define BSTRIDE 80
#define A_BYTES (128 * ASTRIDE)    // 10240
#define B_BYTES (112 * BSTRIDE)    // 8960
#define CSTRIDE 113                // odd float stride -> conflict-free row reads
#define SMEM_DYN (128 * CSTRIDE * 4 + 1024)   // 58880; tile buffers (38400) fit inside

__device__ __half g_Wh[NW * KPAD]; // packed block-structured fp16 weights (2.3 MB)

// ---------------- helpers ----------------
__device__ __forceinline__ uint32_t smem_u32(const void* p) {
    uint32_t a;
    asm("{ .reg .u64 t; cvta.to.shared.u64 t, %1; cvt.u32.u64 %0, t; }" : "=r"(a) : "l"(p));
    return a;
}
__device__ __forceinline__ uint32_t lds32(uint32_t a) {
    uint32_t v;
    asm volatile("ld.shared.b32 %0, [%1];" : "=r"(v) : "r"(a));
    return v;
}
__device__ __forceinline__ void cp16(uint32_t dst, const void* src) {
    asm volatile("cp.async.cg.shared.global [%0], [%1], 16;" :: "r"(dst), "l"(src) : "memory");
}
__device__ __forceinline__ void mma16816(float* c, const uint32_t* a, uint32_t b0, uint32_t b1) {
    asm volatile(
        "mma.sync.aligned.m16n8k16.row.col.f32.f16.f16.f32 "
        "{%0,%1,%2,%3}, {%4,%5,%6,%7}, {%8,%9}, {%0,%1,%2,%3};"
        : "+f"(c[0]), "+f"(c[1]), "+f"(c[2]), "+f"(c[3])
        : "r"(a[0]), "r"(a[1]), "r"(a[2]), "r"(a[3]), "r"(b0), "r"(b1));
}

// ---------------- prep: pack W into [NW][KPAD] fp16 ----------------
// k=0: rate idx (zero row); k in [1,26): genre; [26,2212): director; [2212,10242): actor;
// [10242,KPAD): zero pad. Rows 96/97/98 are count indicator rows (1.0) per segment.
__global__ void prep_w_kernel(const float* __restrict__ Wg,
                              const float* __restrict__ Wd,
                              const float* __restrict__ Wa) {
    int idx = blockIdx.x * blockDim.x + threadIdx.x;
    if (idx >= NW * KPAD) return;
    int n = idx / KPAD;
    int k = idx - n * KPAD;
    float v = 0.0f;
    if (k >= 1 && k < 26) {
        if (n < 32)       v = Wg[n * 25 + (k - 1)];
        else if (n == 96) v = 1.0f;
    } else if (k >= 26 && k < 2212) {
        if (n >= 32 && n < 64) v = Wd[(n - 32) * 2186 + (k - 26)];
        else if (n == 97)      v = 1.0f;
    } else if (k >= 2212 && k < 10242) {
        if (n >= 64 && n < 96) v = Wa[(n - 64) * 8030 + (k - 2212)];
        else if (n == 98)      v = 1.0f;
    }
    g_Wh[idx] = __float2half_rn(v);
}

// ---------------- main kernel ----------------
__global__ void __launch_bounds__(256, 1)
mli_main_kernel(const int* __restrict__ x,
                const float* __restrict__ rate_table,
                float* __restrict__ out) {
    extern __shared__ char smem_raw[];
    const int tid  = threadIdx.x;
    const int wid  = tid >> 5;
    const int lane = tid & 31;
    const int gid  = lane >> 2;
    const int tid4 = lane & 3;
    const int wm   = wid >> 1;         // 0..3 : M warp tile
    const int wn   = wid & 1;          // 0..1 : N warp tile
    const int m_base = blockIdx.x * MT;

    uint32_t sbase = smem_u32(smem_raw);
    uint32_t tb = (sbase + 1023u) & ~1023u;
    const uint32_t Abuf[2] = { tb, tb + A_BYTES };
    const uint32_t Bbuf[2] = { tb + 2u * A_BYTES, tb + 2u * A_BYTES + B_BYTES };

    // A staging: thread handles half a row (16 ints)
    const int arow = tid >> 1;
    const int ah   = tid & 1;
    const int* xrow = x + (size_t)(m_base + arow) * XROW + ah * 16;
    const uint32_t a_dst_off = (uint32_t)(arow * ASTRIDE + ah * 32);

    int2 areg[8];

    auto load_a = [&](int k0, bool tail) {
        if (!tail) {
#pragma unroll
            for (int i = 0; i < 8; ++i) areg[i] = *(const int2*)(xrow + k0 + i * 2);
        } else {
#pragma unroll
            for (int i = 0; i < 8; ++i) {
                int base = k0 + ah * 16 + i * 2;
                int v0 = (base     < XROW) ? xrow[k0 + i * 2]     : 0;
                int v1 = (base + 1 < XROW) ? xrow[k0 + i * 2 + 1] : 0;
                areg[i] = make_int2(v0, v1);
            }
        }
    };
    auto sts_a = [&](int buf) {
        uint32_t d = Abuf[buf] + a_dst_off;
        uint32_t h[8];
#pragma unroll
        for (int i = 0; i < 8; ++i) {
            __half2 hh = __floats2half2_rn((float)areg[i].x, (float)areg[i].y);
            h[i] = *reinterpret_cast<uint32_t*>(&hh);
        }
        asm volatile("st.shared.v4.b32 [%0], {%1,%2,%3,%4};"
                     :: "r"(d), "r"(h[0]), "r"(h[1]), "r"(h[2]), "r"(h[3]) : "memory");
        asm volatile("st.shared.v4.b32 [%0], {%1,%2,%3,%4};"
                     :: "r"(d + 16), "r"(h[4]), "r"(h[5]), "r"(h[6]), "r"(h[7]) : "memory");
    };
    auto cp_b = [&](int k0, int buf) {
#pragma unroll
        for (int i = 0; i < 2; ++i) {
            int c = tid + i * 256;
            if (c < 448) {                       // 112 rows x 4 chunks of 16B
                int n = c >> 2, ch = c & 3;
                cp16(Bbuf[buf] + (uint32_t)(n * BSTRIDE + ch * 16),
                     g_Wh + (size_t)n * KPAD + k0 + ch * 8);
            }
        }
    };

    float acc[2][7][4];
#pragma unroll
    for (int mi = 0; mi < 2; ++mi)
#pragma unroll
        for (int j = 0; j < 7; ++j)
#pragma unroll
            for (int q = 0; q < 4; ++q) acc[mi][j][q] = 0.0f;

    // prologue: stage tile 0
    load_a(0, false);
    cp_b(0, 0);
    asm volatile("cp.async.commit_group;" ::: "memory");
    sts_a(0);

    for (int t = 0; t < NT; ++t) {
        const int buf = t & 1;
        if (t + 1 < NT) {
            load_a((t + 1) * KT, (t + 1) == NT - 1);
            cp_b((t + 1) * KT, buf ^ 1);
            asm volatile("cp.async.commit_group;" ::: "memory");
            asm volatile("cp.async.wait_group 1;" ::: "memory");
        } else {
            asm volatile("cp.async.wait_group 0;" ::: "memory");
        }
        __syncthreads();

        const uint32_t Ab = Abuf[buf], Bb = Bbuf[buf];
#pragma unroll
        for (int ks = 0; ks < 2; ++ks) {
            uint32_t afr[2][4];
#pragma unroll
            for (int mi = 0; mi < 2; ++mi) {
                uint32_t ab = Ab + (uint32_t)((wm * 32 + mi * 16 + gid) * ASTRIDE
                                              + ks * 32 + tid4 * 4);
                afr[mi][0] = lds32(ab);
                afr[mi][1] = lds32(ab + 8 * ASTRIDE);
                afr[mi][2] = lds32(ab + 16);
                afr[mi][3] = lds32(ab + 8 * ASTRIDE + 16);
            }
#pragma unroll
            for (int j = 0; j < 7; ++j) {
                uint32_t bb = Bb + (uint32_t)((wn * 56 + j * 8 + gid) * BSTRIDE
                                              + ks * 32 + tid4 * 4);
                uint32_t b0 = lds32(bb);
                uint32_t b1 = lds32(bb + 16);
                mma16816(acc[0][j], afr[0], b0, b1);
                mma16816(acc[1][j], afr[1], b0, b1);
            }
        }
        __syncthreads();
        if (t + 1 < NT) sts_a(buf ^ 1);
    }

    // ---------------- epilogue ----------------
    // dump accumulators to SMEM (reuses tile buffers; all mma done after trailing sync)
    float* Cs = (float*)(smem_raw + (tb - sbase));
#pragma unroll
    for (int mi = 0; mi < 2; ++mi) {
        int r0 = wm * 32 + mi * 16 + gid;
#pragma unroll
        for (int j = 0; j < 7; ++j) {
            int c0 = wn * 56 + j * 8 + tid4 * 2;
            Cs[r0 * CSTRIDE + c0]           = acc[mi][j][0];
            Cs[r0 * CSTRIDE + c0 + 1]       = acc[mi][j][1];
            Cs[(r0 + 8) * CSTRIDE + c0]     = acc[mi][j][2];
            Cs[(r0 + 8) * CSTRIDE + c0 + 1] = acc[mi][j][3];
        }
    }
    __syncthreads();

    if (tid < 128) {
        const int rg = m_base + tid;
        const float* cr = Cs + tid * CSTRIDE;
        float invg = 1.0f / cr[96];
        float invd = 1.0f / cr[97];
        float inva = 1.0f / cr[98];

        int ridx = x[(size_t)rg * XROW];
        const float4* rt = (const float4*)(rate_table + ridx * 32);
        float4 rv[8];
        float sq = 0.0f;
#pragma unroll
        for (int i = 0; i < 8; ++i) {
            rv[i] = rt[i];
            sq += rv[i].x * rv[i].x + rv[i].y * rv[i].y + rv[i].z * rv[i].z + rv[i].w * rv[i].w;
        }
        float norm = sqrtf(sq);
        float scale = (norm > 1.0f) ? (1.0f / (norm + 1e-7f)) : 1.0f;

        float4* o = (float4*)(out + (size_t)rg * 128);
#pragma unroll
        for (int i = 0; i < 8; ++i)
            o[i] = make_float4(rv[i].x * scale, rv[i].y * scale,
                               rv[i].z * scale, rv[i].w * scale);
#pragma unroll
        for (int i = 0; i < 8; ++i)
            o[8 + i] = make_float4(cr[4 * i + 0] * invg, cr[4 * i + 1] * invg,
                                   cr[4 * i + 2] * invg, cr[4 * i + 3] * invg);
#pragma unroll
        for (int i = 0; i < 8; ++i)
            o[16 + i] = make_float4(cr[32 + 4 * i + 0] * invd, cr[32 + 4 * i + 1] * invd,
                                    cr[32 + 4 * i + 2] * invd, cr[32 + 4 * i + 3] * invd);
#pragma unroll
        for (int i = 0; i < 8; ++i)
            o[24 + i] = make_float4(cr[64 + 4 * i + 0] * inva, cr[64 + 4 * i + 1] * inva,
                                    cr[64 + 4 * i + 2] * inva, cr[64 + 4 * i + 3] * inva);
    }
}

// ---------------- launch ----------------
extern "C" void kernel_launch(void* const* d_in, const int* in_sizes, int n_in,
                              void* d_out, int out_size) {
    (void)in_sizes; (void)n_in; (void)out_size;
    const int*   x    = (const int*)d_in[0];
    const float* rate = (const float*)d_in[1];
    const float* Wg   = (const float*)d_in[2];
    const float* Wd   = (const float*)d_in[3];
    const float* Wa   = (const float*)d_in[4];
    float*       out  = (float*)d_out;

    prep_w_kernel<<<(NW * KPAD + 255) / 256, 256>>>(Wg, Wd, Wa);

    cudaFuncSetAttribute(mli_main_kernel,
                         cudaFuncAttributeMaxDynamicSharedMemorySize, SMEM_DYN);
    mli_main_kernel<<<BROWS / MT, 256, SMEM_DYN>>>(x, rate, out);
}

// round 12
// speedup vs baseline: 1.0777x; 1.0409x over previous
#include <cuda_runtime.h>
#include <cuda_fp16.h>
#include <cstdint>
#include <cstddef>

#define XROW 10242
#define BROWS 16384
#define KT 64
#define NT 161                     // ceil(10242/64)
#define KPAD (NT * KT)             // 10304
#define NW 112                     // 96 emb cols + 3 count cols + pad
#define MT 64
#define ASTRIDE 144                // 64 halves (128B) + 16B pad -> stride 36 banks == 4 mod 32
#define BSTRIDE 144
#define A_BYTES (MT * ASTRIDE)     // 9216
#define B_BYTES (NW * BSTRIDE)     // 16128
#define CSTRIDE 113
#define SMEM_DYN (2 * A_BYTES + 2 * B_BYTES + 1024)   // 51712 (C 64*113*4=28928 overlaid)

__device__ __half g_Wh[NW * KPAD]; // packed block-structured fp16 weights (~2.3 MB)

// ---------------- helpers ----------------
__device__ __forceinline__ uint32_t smem_u32(const void* p) {
    uint32_t a;
    asm("{ .reg .u64 t; cvta.to.shared.u64 t, %1; cvt.u32.u64 %0, t; }" : "=r"(a) : "l"(p));
    return a;
}
__device__ __forceinline__ void cp16(uint32_t dst, const void* src) {
    asm volatile("cp.async.cg.shared.global [%0], [%1], 16;" :: "r"(dst), "l"(src) : "memory");
}
__device__ __forceinline__ void ldsm4(uint32_t* r, uint32_t a) {
    asm volatile("ldmatrix.sync.aligned.m8n8.x4.shared.b16 {%0,%1,%2,%3}, [%4];"
                 : "=r"(r[0]), "=r"(r[1]), "=r"(r[2]), "=r"(r[3]) : "r"(a));
}
__device__ __forceinline__ void ldsm2(uint32_t* r, uint32_t a) {
    asm volatile("ldmatrix.sync.aligned.m8n8.x2.shared.b16 {%0,%1}, [%2];"
                 : "=r"(r[0]), "=r"(r[1]) : "r"(a));
}
__device__ __forceinline__ void mma16816(float* c, const uint32_t* a, uint32_t b0, uint32_t b1) {
    asm volatile(
        "mma.sync.aligned.m16n8k16.row.col.f32.f16.f16.f32 "
        "{%0,%1,%2,%3}, {%4,%5,%6,%7}, {%8,%9}, {%0,%1,%2,%3};"
        : "+f"(c[0]), "+f"(c[1]), "+f"(c[2]), "+f"(c[3])
        : "r"(a[0]), "r"(a[1]), "r"(a[2]), "r"(a[3]), "r"(b0), "r"(b1));
}

// ---------------- prep: pack W into [NW][KPAD] fp16 ----------------
// k=0: rate idx (zero row); [1,26): genre; [26,2212): director; [2212,10242): actor;
// [10242,KPAD): zero pad. Rows 96/97/98 = count indicator rows (1.0) per segment.
__global__ void prep_w_kernel(const float* __restrict__ Wg,
                              const float* __restrict__ Wd,
                              const float* __restrict__ Wa) {
    int idx = blockIdx.x * blockDim.x + threadIdx.x;
    if (idx >= NW * KPAD) return;
    int n = idx / KPAD;
    int k = idx - n * KPAD;
    float v = 0.0f;
    if (k >= 1 && k < 26) {
        if (n < 32)       v = Wg[n * 25 + (k - 1)];
        else if (n == 96) v = 1.0f;
    } else if (k >= 26 && k < 2212) {
        if (n >= 32 && n < 64) v = Wd[(n - 32) * 2186 + (k - 26)];
        else if (n == 97)      v = 1.0f;
    } else if (k >= 2212 && k < 10242) {
        if (n >= 64 && n < 96) v = Wa[(n - 64) * 8030 + (k - 2212)];
        else if (n == 98)      v = 1.0f;
    }
    g_Wh[idx] = __float2half_rn(v);
}

// ---------------- main kernel ----------------
__global__ void __launch_bounds__(256, 2)
mli_main_kernel(const int* __restrict__ x,
                const float* __restrict__ rate_table,
                float* __restrict__ out) {
    extern __shared__ char smem_raw[];
    const int tid  = threadIdx.x;
    const int wid  = tid >> 5;
    const int lane = tid & 31;
    const int gid  = lane >> 2;
    const int tid4 = lane & 3;
    const int wm   = wid >> 1;         // 0..3 : 16-row M slice
    const int wn   = wid & 1;          // 0..1 : 56-col N slice
    const int m_base = blockIdx.x * MT;

    uint32_t sbase = smem_u32(smem_raw);
    uint32_t tb = (sbase + 1023u) & ~1023u;
    const uint32_t Abuf[2] = { tb, tb + A_BYTES };
    const uint32_t Bbuf[2] = { tb + 2u * A_BYTES, tb + 2u * A_BYTES + B_BYTES };

    // A staging: thread = (row, quarter) -> 16 ints
    const int arow = tid >> 2;
    const int aq   = tid & 3;
    const int* xrow = x + (size_t)(m_base + arow) * XROW + aq * 16;
    const uint32_t a_dst_off = (uint32_t)(arow * ASTRIDE + aq * 32);

    int2 areg[8];
    auto load_a = [&](int k0, bool tail) {
        if (!tail) {
#pragma unroll
            for (int i = 0; i < 8; ++i) areg[i] = *(const int2*)(xrow + k0 + i * 2);
        } else {
#pragma unroll
            for (int i = 0; i < 8; ++i) {
                int base = k0 + aq * 16 + i * 2;
                int v0 = (base     < XROW) ? xrow[k0 + i * 2]     : 0;
                int v1 = (base + 1 < XROW) ? xrow[k0 + i * 2 + 1] : 0;
                areg[i] = make_int2(v0, v1);
            }
        }
    };
    auto sts_a = [&](int buf) {
        uint32_t d = Abuf[buf] + a_dst_off;
        uint32_t h[8];
#pragma unroll
        for (int i = 0; i < 8; ++i) {
            __half2 hh = __floats2half2_rn((float)areg[i].x, (float)areg[i].y);
            h[i] = *reinterpret_cast<uint32_t*>(&hh);
        }
        asm volatile("st.shared.v4.b32 [%0], {%1,%2,%3,%4};"
                     :: "r"(d), "r"(h[0]), "r"(h[1]), "r"(h[2]), "r"(h[3]) : "memory");
        asm volatile("st.shared.v4.b32 [%0], {%1,%2,%3,%4};"
                     :: "r"(d + 16), "r"(h[4]), "r"(h[5]), "r"(h[6]), "r"(h[7]) : "memory");
    };
    auto cp_b = [&](int k0, int buf) {
#pragma unroll
        for (int i = 0; i < 4; ++i) {
            int c = tid + i * 256;
            if (c < 896) {                       // 112 rows x 8 chunks of 16B
                int n = c >> 3, ch = c & 7;
                cp16(Bbuf[buf] + (uint32_t)(n * BSTRIDE + ch * 16),
                     g_Wh + (size_t)n * KPAD + k0 + ch * 8);
            }
        }
    };

    // ldmatrix lane-address offsets (byte offsets within a tile buffer)
    const uint32_t a_off =
        (uint32_t)((wm * 16 + ((lane >> 3) & 1) * 8 + (lane & 7)) * ASTRIDE
                   + (lane >> 4) * 16);
    uint32_t b_off[3];
#pragma unroll
    for (int jp = 0; jp < 3; ++jp)
        b_off[jp] = (uint32_t)((wn * 56 + jp * 16 + (lane >> 4) * 8 + (lane & 7)) * BSTRIDE
                               + ((lane >> 3) & 1) * 16);
    const uint32_t b_off2 =
        (uint32_t)((wn * 56 + 48 + (lane & 7)) * BSTRIDE + ((lane >> 3) & 1) * 16);

    float acc[7][4];
#pragma unroll
    for (int j = 0; j < 7; ++j)
#pragma unroll
        for (int q = 0; q < 4; ++q) acc[j][q] = 0.0f;

    // prologue: stage tile 0
    load_a(0, false);
    cp_b(0, 0);
    asm volatile("cp.async.commit_group;" ::: "memory");
    sts_a(0);

    for (int t = 0; t < NT; ++t) {
        const int buf = t & 1;
        if (t + 1 < NT) {
            load_a((t + 1) * KT, (t + 1) == NT - 1);
            cp_b((t + 1) * KT, buf ^ 1);
            asm volatile("cp.async.commit_group;" ::: "memory");
            asm volatile("cp.async.wait_group 1;" ::: "memory");
        } else {
            asm volatile("cp.async.wait_group 0;" ::: "memory");
        }
        __syncthreads();

        const uint32_t Ab = Abuf[buf], Bb = Bbuf[buf];
#pragma unroll
        for (int ks = 0; ks < 4; ++ks) {
            uint32_t afr[4];
            ldsm4(afr, Ab + a_off + ks * 32);
            uint32_t bfr[7][2];
#pragma unroll
            for (int jp = 0; jp < 3; ++jp) {
                uint32_t t4[4];
                ldsm4(t4, Bb + b_off[jp] + ks * 32);
                bfr[2 * jp][0] = t4[0]; bfr[2 * jp][1] = t4[1];
                bfr[2 * jp + 1][0] = t4[2]; bfr[2 * jp + 1][1] = t4[3];
            }
            ldsm2(bfr[6], Bb + b_off2 + ks * 32);
#pragma unroll
            for (int j = 0; j < 7; ++j)
                mma16816(acc[j], afr, bfr[j][0], bfr[j][1]);
        }
        __syncthreads();
        if (t + 1 < NT) sts_a(buf ^ 1);
    }

    // ---------------- epilogue ----------------
    float* Cs = (float*)(smem_raw + (tb - sbase));
    {
        int r0 = wm * 16 + gid;
#pragma unroll
        for (int j = 0; j < 7; ++j) {
            int c0 = wn * 56 + j * 8 + tid4 * 2;
            Cs[r0 * CSTRIDE + c0]           = acc[j][0];
            Cs[r0 * CSTRIDE + c0 + 1]       = acc[j][1];
            Cs[(r0 + 8) * CSTRIDE + c0]     = acc[j][2];
            Cs[(r0 + 8) * CSTRIDE + c0 + 1] = acc[j][3];
        }
    }
    __syncthreads();

    {
        const int row = tid >> 2;          // 0..63
        const int seg = tid & 3;           // 0: rate, 1: genre, 2: director, 3: actor
        const int rg  = m_base + row;
        const float* cr = Cs + row * CSTRIDE;
        float4* o = (float4*)(out + (size_t)rg * 128);

        if (seg == 0) {
            int ridx = x[(size_t)rg * XROW];
            const float4* rt = (const float4*)(rate_table + ridx * 32);
            float4 rv[8];
            float sq = 0.0f;
#pragma unroll
            for (int i = 0; i < 8; ++i) {
                rv[i] = rt[i];
                sq += rv[i].x * rv[i].x + rv[i].y * rv[i].y
                    + rv[i].z * rv[i].z + rv[i].w * rv[i].w;
            }
            float norm = sqrtf(sq);
            float scale = (norm > 1.0f) ? (1.0f / (norm + 1e-7f)) : 1.0f;
#pragma unroll
            for (int i = 0; i < 8; ++i)
                o[i] = make_float4(rv[i].x * scale, rv[i].y * scale,
                                   rv[i].z * scale, rv[i].w * scale);
        } else {
            float inv = 1.0f / cr[95 + seg];
            const float* src = cr + (seg - 1) * 32;
#pragma unroll
            for (int i = 0; i < 8; ++i)
                o[seg * 8 + i] = make_float4(src[4 * i + 0] * inv, src[4 * i + 1] * inv,
                                             src[4 * i + 2] * inv, src[4 * i + 3] * inv);
        }
    }
}

// ---------------- launch ----------------
extern "C" void kernel_launch(void* const* d_in, const int* in_sizes, int n_in,
                              void* d_out, int out_size) {
    (void)in_sizes; (void)n_in; (void)out_size;
    const int*   x    = (const int*)d_in[0];
    const float* rate = (const float*)d_in[1];
    const float* Wg   = (const float*)d_in[2];
    const float* Wd   = (const float*)d_in[3];
    const float* Wa   = (const float*)d_in[4];
    float*       out  = (float*)d_out;

    prep_w_kernel<<<(NW * KPAD + 255) / 256, 256>>>(Wg, Wd, Wa);

    cudaFuncSetAttribute(mli_main_kernel,
                         cudaFuncAttributeMaxDynamicSharedMemorySize, SMEM_DYN);
    mli_main_kernel<<<BROWS / MT, 256, SMEM_DYN>>>(x, rate, out);
}

// round 13
// speedup vs baseline: 1.0786x; 1.0008x over previous
#include <cuda_runtime.h>
#include <cuda_fp16.h>
#include <cstdint>
#include <cstddef>

#define XROW 10242
#define BROWS 16384
#define KT 64
#define NT 161                     // ceil(10242/64)
#define KPAD (NT * KT)             // 10304
#define NW 112                     // 96 emb cols + 3 count cols + pad
#define MT 64
#define ASTRIDE 144                // 64 halves (128B) + 16B pad -> stride 36 banks == 4 mod 32
#define BSTRIDE 144
#define A_BYTES (MT * ASTRIDE)     // 9216
#define B_BYTES (NW * BSTRIDE)     // 16128
#define CSTRIDE 113
#define SMEM_DYN (2 * A_BYTES + 2 * B_BYTES + 1024)   // 51712 (C 64*113*4=28928 overlaid)

__device__ __half g_Wh[NW * KPAD]; // packed block-structured fp16 weights (~2.3 MB)

// ---------------- helpers ----------------
__device__ __forceinline__ uint32_t smem_u32(const void* p) {
    uint32_t a;
    asm("{ .reg .u64 t; cvta.to.shared.u64 t, %1; cvt.u32.u64 %0, t; }" : "=r"(a) : "l"(p));
    return a;
}
__device__ __forceinline__ void cp16(uint32_t dst, const void* src) {
    asm volatile("cp.async.cg.shared.global [%0], [%1], 16;" :: "r"(dst), "l"(src) : "memory");
}
__device__ __forceinline__ void ldsm4(uint32_t* r, uint32_t a) {
    asm volatile("ldmatrix.sync.aligned.m8n8.x4.shared.b16 {%0,%1,%2,%3}, [%4];"
                 : "=r"(r[0]), "=r"(r[1]), "=r"(r[2]), "=r"(r[3]) : "r"(a));
}
__device__ __forceinline__ void ldsm2(uint32_t* r, uint32_t a) {
    asm volatile("ldmatrix.sync.aligned.m8n8.x2.shared.b16 {%0,%1}, [%2];"
                 : "=r"(r[0]), "=r"(r[1]) : "r"(a));
}
__device__ __forceinline__ void mma16816(float* c, const uint32_t* a, uint32_t b0, uint32_t b1) {
    asm volatile(
        "mma.sync.aligned.m16n8k16.row.col.f32.f16.f16.f32 "
        "{%0,%1,%2,%3}, {%4,%5,%6,%7}, {%8,%9}, {%0,%1,%2,%3};"
        : "+f"(c[0]), "+f"(c[1]), "+f"(c[2]), "+f"(c[3])
        : "r"(a[0]), "r"(a[1]), "r"(a[2]), "r"(a[3]), "r"(b0), "r"(b1));
}

// ---------------- prep: pack W into [NW][KPAD] fp16 ----------------
// k=0: rate idx (zero row); [1,26): genre; [26,2212): director; [2212,10242): actor;
// [10242,KPAD): zero pad. Rows 96/97/98 = count indicator rows (1.0) per segment.
__global__ void prep_w_kernel(const float* __restrict__ Wg,
                              const float* __restrict__ Wd,
                              const float* __restrict__ Wa) {
    int idx = blockIdx.x * blockDim.x + threadIdx.x;
    if (idx >= NW * KPAD) return;
    int n = idx / KPAD;
    int k = idx - n * KPAD;
    float v = 0.0f;
    if (k >= 1 && k < 26) {
        if (n < 32)       v = Wg[n * 25 + (k - 1)];
        else if (n == 96) v = 1.0f;
    } else if (k >= 26 && k < 2212) {
        if (n >= 32 && n < 64) v = Wd[(n - 32) * 2186 + (k - 26)];
        else if (n == 97)      v = 1.0f;
    } else if (k >= 2212 && k < 10242) {
        if (n >= 64 && n < 96) v = Wa[(n - 64) * 8030 + (k - 2212)];
        else if (n == 98)      v = 1.0f;
    }
    g_Wh[idx] = __float2half_rn(v);
}

// ---------------- main kernel ----------------
__global__ void __launch_bounds__(256, 2)
mli_main_kernel(const int* __restrict__ x,
                const float* __restrict__ rate_table,
                float* __restrict__ out) {
    extern __shared__ char smem_raw[];
    const int tid  = threadIdx.x;
    const int wid  = tid >> 5;
    const int lane = tid & 31;
    const int gid  = lane >> 2;
    const int tid4 = lane & 3;
    const int wm   = wid >> 1;         // 0..3 : 16-row M slice
    const int wn   = wid & 1;          // 0..1 : 56-col N slice
    const int m_base = blockIdx.x * MT;

    uint32_t sbase = smem_u32(smem_raw);
    uint32_t tb = (sbase + 1023u) & ~1023u;
    const uint32_t Abuf[2] = { tb, tb + A_BYTES };
    const uint32_t Bbuf[2] = { tb + 2u * A_BYTES, tb + 2u * A_BYTES + B_BYTES };

    // A staging: thread = (row, quarter) -> 16 ints
    const int arow = tid >> 2;
    const int aq   = tid & 3;
    const int* xrow = x + (size_t)(m_base + arow) * XROW + aq * 16;
    const uint32_t a_dst_off = (uint32_t)(arow * ASTRIDE + aq * 32);

    int2 areg[8];
    auto load_a = [&](int k0, bool tail) {
        if (!tail) {
#pragma unroll
            for (int i = 0; i < 8; ++i) areg[i] = *(const int2*)(xrow + k0 + i * 2);
        } else {
#pragma unroll
            for (int i = 0; i < 8; ++i) {
                int base = k0 + aq * 16 + i * 2;
                int v0 = (base     < XROW) ? xrow[k0 + i * 2]     : 0;
                int v1 = (base + 1 < XROW) ? xrow[k0 + i * 2 + 1] : 0;
                areg[i] = make_int2(v0, v1);
            }
        }
    };
    auto sts_a = [&](int buf) {
        uint32_t d = Abuf[buf] + a_dst_off;
        uint32_t h[8];
#pragma unroll
        for (int i = 0; i < 8; ++i) {
            __half2 hh = __floats2half2_rn((float)areg[i].x, (float)areg[i].y);
            h[i] = *reinterpret_cast<uint32_t*>(&hh);
        }
        asm volatile("st.shared.v4.b32 [%0], {%1,%2,%3,%4};"
                     :: "r"(d), "r"(h[0]), "r"(h[1]), "r"(h[2]), "r"(h[3]) : "memory");
        asm volatile("st.shared.v4.b32 [%0], {%1,%2,%3,%4};"
                     :: "r"(d + 16), "r"(h[4]), "r"(h[5]), "r"(h[6]), "r"(h[7]) : "memory");
    };
    auto cp_b = [&](int k0, int buf) {
#pragma unroll
        for (int i = 0; i < 4; ++i) {
            int c = tid + i * 256;
            if (c < 896) {                       // 112 rows x 8 chunks of 16B
                int n = c >> 3, ch = c & 7;
                cp16(Bbuf[buf] + (uint32_t)(n * BSTRIDE + ch * 16),
                     g_Wh + (size_t)n * KPAD + k0 + ch * 8);
            }
        }
    };

    // ldmatrix lane-address offsets (byte offsets within a tile buffer)
    const uint32_t a_off =
        (uint32_t)((wm * 16 + ((lane >> 3) & 1) * 8 + (lane & 7)) * ASTRIDE
                   + (lane >> 4) * 16);
    uint32_t b_off[3];
#pragma unroll
    for (int jp = 0; jp < 3; ++jp)
        b_off[jp] = (uint32_t)((wn * 56 + jp * 16 + (lane >> 4) * 8 + (lane & 7)) * BSTRIDE
                               + ((lane >> 3) & 1) * 16);
    const uint32_t b_off2 =
        (uint32_t)((wn * 56 + 48 + (lane & 7)) * BSTRIDE + ((lane >> 3) & 1) * 16);

    float acc[7][4];
#pragma unroll
    for (int j = 0; j < 7; ++j)
#pragma unroll
        for (int q = 0; q < 4; ++q) acc[j][q] = 0.0f;

    // prologue: stage tile 0
    load_a(0, false);
    cp_b(0, 0);
    asm volatile("cp.async.commit_group;" ::: "memory");
    sts_a(0);

    for (int t = 0; t < NT; ++t) {
        const int buf = t & 1;
        if (t + 1 < NT) {
            load_a((t + 1) * KT, (t + 1) == NT - 1);
            cp_b((t + 1) * KT, buf ^ 1);
            asm volatile("cp.async.commit_group;" ::: "memory");
            asm volatile("cp.async.wait_group 1;" ::: "memory");
        } else {
            asm volatile("cp.async.wait_group 0;" ::: "memory");
        }
        __syncthreads();

        const uint32_t Ab = Abuf[buf], Bb = Bbuf[buf];
#pragma unroll
        for (int ks = 0; ks < 4; ++ks) {
            uint32_t afr[4];
            ldsm4(afr, Ab + a_off + ks * 32);
            uint32_t bfr[7][2];
#pragma unroll
            for (int jp = 0; jp < 3; ++jp) {
                uint32_t t4[4];
                ldsm4(t4, Bb + b_off[jp] + ks * 32);
                bfr[2 * jp][0] = t4[0]; bfr[2 * jp][1] = t4[1];
                bfr[2 * jp + 1][0] = t4[2]; bfr[2 * jp + 1][1] = t4[3];
            }
            ldsm2(bfr[6], Bb + b_off2 + ks * 32);
#pragma unroll
            for (int j = 0; j < 7; ++j)
                mma16816(acc[j], afr, bfr[j][0], bfr[j][1]);
        }
        __syncthreads();
        if (t + 1 < NT) sts_a(buf ^ 1);
    }

    // ---------------- epilogue ----------------
    float* Cs = (float*)(smem_raw + (tb - sbase));
    {
        int r0 = wm * 16 + gid;
#pragma unroll
        for (int j = 0; j < 7; ++j) {
            int c0 = wn * 56 + j * 8 + tid4 * 2;
            Cs[r0 * CSTRIDE + c0]           = acc[j][0];
            Cs[r0 * CSTRIDE + c0 + 1]       = acc[j][1];
            Cs[(r0 + 8) * CSTRIDE + c0]     = acc[j][2];
            Cs[(r0 + 8) * CSTRIDE + c0 + 1] = acc[j][3];
        }
    }
    __syncthreads();

    {
        const int row = tid >> 2;          // 0..63
        const int seg = tid & 3;           // 0: rate, 1: genre, 2: director, 3: actor
        const int rg  = m_base + row;
        const float* cr = Cs + row * CSTRIDE;
        float4* o = (float4*)(out + (size_t)rg * 128);

        if (seg == 0) {
            int ridx = x[(size_t)rg * XROW];
            const float4* rt = (const float4*)(rate_table + ridx * 32);
            float4 rv[8];
            float sq = 0.0f;
#pragma unroll
            for (int i = 0; i < 8; ++i) {
                rv[i] = rt[i];
                sq += rv[i].x * rv[i].x + rv[i].y * rv[i].y
                    + rv[i].z * rv[i].z + rv[i].w * rv[i].w;
            }
            float norm = sqrtf(sq);
            float scale = (norm > 1.0f) ? (1.0f / (norm + 1e-7f)) : 1.0f;
#pragma unroll
            for (int i = 0; i < 8; ++i)
                o[i] = make_float4(rv[i].x * scale, rv[i].y * scale,
                                   rv[i].z * scale, rv[i].w * scale);
        } else {
            float inv = 1.0f / cr[95 + seg];
            const float* src = cr + (seg - 1) * 32;
#pragma unroll
            for (int i = 0; i < 8; ++i)
                o[seg * 8 + i] = make_float4(src[4 * i + 0] * inv, src[4 * i + 1] * inv,
                                             src[4 * i + 2] * inv, src[4 * i + 3] * inv);
        }
    }
}

// ---------------- launch ----------------
extern "C" void kernel_launch(void* const* d_in, const int* in_sizes, int n_in,
                              void* d_out, int out_size) {
    (void)in_sizes; (void)n_in; (void)out_size;
    const int*   x    = (const int*)d_in[0];
    const float* rate = (const float*)d_in[1];
    const float* Wg   = (const float*)d_in[2];
    const float* Wd   = (const float*)d_in[3];
    const float* Wa   = (const float*)d_in[4];
    float*       out  = (float*)d_out;

    prep_w_kernel<<<(NW * KPAD + 255) / 256, 256>>>(Wg, Wd, Wa);

    cudaFuncSetAttribute(mli_main_kernel,
                         cudaFuncAttributeMaxDynamicSharedMemorySize, SMEM_DYN);
    mli_main_kernel<<<BROWS / MT, 256, SMEM_DYN>>>(x, rate, out);
}

// round 14
// speedup vs baseline: 1.5179x; 1.4073x over previous
#include <cuda_runtime.h>
#include <cuda_fp16.h>
#include <cstdint>
#include <cstddef>

#define XROW 10242
#define BROWS 16384
#define KT 64
#define NT 161                     // ceil(10242/64)
#define KPAD (NT * KT)             // 10304
#define NW 112                     // 96 emb cols + 3 count cols + pad
#define MT 64
#define ASTRIDE 144                // 64 halves (128B) + 16B pad -> row stride 36 banks == 4 mod 32
#define BSTRIDE 144
#define A_BYTES (MT * ASTRIDE)     // 9216
#define B_BYTES (NW * BSTRIDE)     // 16128
#define CSTRIDE 113
#define SMEM_DYN (2 * A_BYTES + 2 * B_BYTES + 1024)   // 51712 (C 64*113*4=28928 overlaid)

__device__ __half g_Wh[NW * KPAD]; // packed block-structured fp16 weights (~2.3 MB)

// ---------------- helpers ----------------
__device__ __forceinline__ uint32_t smem_u32(const void* p) {
    uint32_t a;
    asm("{ .reg .u64 t; cvta.to.shared.u64 t, %1; cvt.u32.u64 %0, t; }" : "=r"(a) : "l"(p));
    return a;
}
__device__ __forceinline__ void cp16(uint32_t dst, const void* src) {
    asm volatile("cp.async.cg.shared.global [%0], [%1], 16;" :: "r"(dst), "l"(src) : "memory");
}
__device__ __forceinline__ int2 ldcs64(const int* p) {
    int2 v;
    asm volatile("ld.global.cs.v2.s32 {%0,%1}, [%2];" : "=r"(v.x), "=r"(v.y) : "l"(p));
    return v;
}
__device__ __forceinline__ void ldsm4(uint32_t* r, uint32_t a) {
    asm volatile("ldmatrix.sync.aligned.m8n8.x4.shared.b16 {%0,%1,%2,%3}, [%4];"
                 : "=r"(r[0]), "=r"(r[1]), "=r"(r[2]), "=r"(r[3]) : "r"(a));
}
__device__ __forceinline__ void ldsm2(uint32_t* r, uint32_t a) {
    asm volatile("ldmatrix.sync.aligned.m8n8.x2.shared.b16 {%0,%1}, [%2];"
                 : "=r"(r[0]), "=r"(r[1]) : "r"(a));
}
__device__ __forceinline__ void mma16816(float* c, const uint32_t* a, uint32_t b0, uint32_t b1) {
    asm volatile(
        "mma.sync.aligned.m16n8k16.row.col.f32.f16.f16.f32 "
        "{%0,%1,%2,%3}, {%4,%5,%6,%7}, {%8,%9}, {%0,%1,%2,%3};"
        : "+f"(c[0]), "+f"(c[1]), "+f"(c[2]), "+f"(c[3])
        : "r"(a[0]), "r"(a[1]), "r"(a[2]), "r"(a[3]), "r"(b0), "r"(b1));
}

// ---------------- prep: pack W into [NW][KPAD] fp16 ----------------
// k=0: rate idx (zero row); [1,26): genre; [26,2212): director; [2212,10242): actor;
// [10242,KPAD): zero pad. Rows 96/97/98 = count indicator rows (1.0) per segment.
__global__ void prep_w_kernel(const float* __restrict__ Wg,
                              const float* __restrict__ Wd,
                              const float* __restrict__ Wa) {
    int idx = blockIdx.x * blockDim.x + threadIdx.x;
    if (idx >= NW * KPAD) return;
    int n = idx / KPAD;
    int k = idx - n * KPAD;
    float v = 0.0f;
    if (k >= 1 && k < 26) {
        if (n < 32)       v = Wg[n * 25 + (k - 1)];
        else if (n == 96) v = 1.0f;
    } else if (k >= 26 && k < 2212) {
        if (n >= 32 && n < 64) v = Wd[(n - 32) * 2186 + (k - 26)];
        else if (n == 97)      v = 1.0f;
    } else if (k >= 2212 && k < 10242) {
        if (n >= 64 && n < 96) v = Wa[(n - 64) * 8030 + (k - 2212)];
        else if (n == 98)      v = 1.0f;
    }
    g_Wh[idx] = __float2half_rn(v);
}

// ---------------- main kernel ----------------
__global__ void __launch_bounds__(256, 2)
mli_main_kernel(const int* __restrict__ x,
                const float* __restrict__ rate_table,
                float* __restrict__ out) {
    extern __shared__ char smem_raw[];
    const int tid  = threadIdx.x;
    const int wid  = tid >> 5;
    const int lane = tid & 31;
    const int gid  = lane >> 2;
    const int tid4 = lane & 3;
    const int wm   = wid >> 1;         // 0..3 : 16-row M slice
    const int wn   = wid & 1;          // 0..1 : 56-col N slice
    const int m_base = blockIdx.x * MT;

    uint32_t sbase = smem_u32(smem_raw);
    uint32_t tb = (sbase + 1023u) & ~1023u;
    const uint32_t Abuf[2] = { tb, tb + A_BYTES };
    const uint32_t Bbuf[2] = { tb + 2u * A_BYTES, tb + 2u * A_BYTES + B_BYTES };

    // A staging: warp w handles rows w, w+8, ..., w+56; lane l loads int2 at col 2l.
    // LDG: 256B warp-contiguous (2-3 lines). STS: bank (36*row + lane) % 32 -> conflict-free.
    const int* xbase = x + (size_t)(m_base + wid) * XROW + 2 * lane;
    const uint32_t a_dst = (uint32_t)(wid * ASTRIDE + lane * 4);

    int2 areg[8];
    auto load_a = [&](int k0, bool tail) {
        if (!tail) {
#pragma unroll
            for (int p = 0; p < 8; ++p)
                areg[p] = ldcs64(xbase + (size_t)p * 8 * XROW + k0);
        } else {
            int c0 = k0 + 2 * lane;
#pragma unroll
            for (int p = 0; p < 8; ++p) {
                const int* src = xbase + (size_t)p * 8 * XROW + k0;
                int v0 = (c0     < XROW) ? src[0] : 0;
                int v1 = (c0 + 1 < XROW) ? src[1] : 0;
                areg[p] = make_int2(v0, v1);
            }
        }
    };
    auto sts_a = [&](int buf) {
#pragma unroll
        for (int p = 0; p < 8; ++p) {
            __half2 hh = __floats2half2_rn((float)areg[p].x, (float)areg[p].y);
            asm volatile("st.shared.b32 [%0], %1;"
                         :: "r"(Abuf[buf] + a_dst + (uint32_t)(p * 8 * ASTRIDE)),
                            "r"(*reinterpret_cast<uint32_t*>(&hh)) : "memory");
        }
    };
    auto cp_b = [&](int k0, int buf) {
#pragma unroll
        for (int i = 0; i < 4; ++i) {
            int c = tid + i * 256;
            if (c < 896) {                       // 112 rows x 8 chunks of 16B
                int n = c >> 3, ch = c & 7;
                cp16(Bbuf[buf] + (uint32_t)(n * BSTRIDE + ch * 16),
                     g_Wh + (size_t)n * KPAD + k0 + ch * 8);
            }
        }
    };

    // ldmatrix lane-address offsets (byte offsets within a tile buffer)
    const uint32_t a_off =
        (uint32_t)((wm * 16 + ((lane >> 3) & 1) * 8 + (lane & 7)) * ASTRIDE
                   + (lane >> 4) * 16);
    uint32_t b_off[3];
#pragma unroll
    for (int jp = 0; jp < 3; ++jp)
        b_off[jp] = (uint32_t)((wn * 56 + jp * 16 + (lane >> 4) * 8 + (lane & 7)) * BSTRIDE
                               + ((lane >> 3) & 1) * 16);
    const uint32_t b_off2 =
        (uint32_t)((wn * 56 + 48 + (lane & 7)) * BSTRIDE + ((lane >> 3) & 1) * 16);

    float acc[7][4];
#pragma unroll
    for (int j = 0; j < 7; ++j)
#pragma unroll
        for (int q = 0; q < 4; ++q) acc[j][q] = 0.0f;

    // prologue: stage tile 0
    load_a(0, false);
    cp_b(0, 0);
    asm volatile("cp.async.commit_group;" ::: "memory");
    sts_a(0);

    for (int t = 0; t < NT; ++t) {
        const int buf = t & 1;
        if (t + 1 < NT) {
            load_a((t + 1) * KT, (t + 1) == NT - 1);
            cp_b((t + 1) * KT, buf ^ 1);
            asm volatile("cp.async.commit_group;" ::: "memory");
            asm volatile("cp.async.wait_group 1;" ::: "memory");
        } else {
            asm volatile("cp.async.wait_group 0;" ::: "memory");
        }
        __syncthreads();

        const uint32_t Ab = Abuf[buf], Bb = Bbuf[buf];
#pragma unroll
        for (int ks = 0; ks < 4; ++ks) {
            uint32_t afr[4];
            ldsm4(afr, Ab + a_off + ks * 32);
            uint32_t bfr[7][2];
#pragma unroll
            for (int jp = 0; jp < 3; ++jp) {
                uint32_t t4[4];
                ldsm4(t4, Bb + b_off[jp] + ks * 32);
                bfr[2 * jp][0] = t4[0]; bfr[2 * jp][1] = t4[1];
                bfr[2 * jp + 1][0] = t4[2]; bfr[2 * jp + 1][1] = t4[3];
            }
            ldsm2(bfr[6], Bb + b_off2 + ks * 32);
#pragma unroll
            for (int j = 0; j < 7; ++j)
                mma16816(acc[j], afr, bfr[j][0], bfr[j][1]);
        }
        __syncthreads();
        if (t + 1 < NT) sts_a(buf ^ 1);
    }

    // ---------------- epilogue ----------------
    float* Cs = (float*)(smem_raw + (tb - sbase));
    {
        int r0 = wm * 16 + gid;
#pragma unroll
        for (int j = 0; j < 7; ++j) {
            int c0 = wn * 56 + j * 8 + tid4 * 2;
            Cs[r0 * CSTRIDE + c0]           = acc[j][0];
            Cs[r0 * CSTRIDE + c0 + 1]       = acc[j][1];
            Cs[(r0 + 8) * CSTRIDE + c0]     = acc[j][2];
            Cs[(r0 + 8) * CSTRIDE + c0 + 1] = acc[j][3];
        }
    }
    __syncthreads();

    {
        const int row = tid >> 2;          // 0..63
        const int seg = tid & 3;           // 0: rate, 1: genre, 2: director, 3: actor
        const int rg  = m_base + row;
        const float* cr = Cs + row * CSTRIDE;
        float4* o = (float4*)(out + (size_t)rg * 128);

        if (seg == 0) {
            int ridx = x[(size_t)rg * XROW];
            const float4* rt = (const float4*)(rate_table + ridx * 32);
            float4 rv[8];
            float sq = 0.0f;
#pragma unroll
            for (int i = 0; i < 8; ++i) {
                rv[i] = rt[i];
                sq += rv[i].x * rv[i].x + rv[i].y * rv[i].y
                    + rv[i].z * rv[i].z + rv[i].w * rv[i].w;
            }
            float norm = sqrtf(sq);
            float scale = (norm > 1.0f) ? (1.0f / (norm + 1e-7f)) : 1.0f;
#pragma unroll
            for (int i = 0; i < 8; ++i)
                o[i] = make_float4(rv[i].x * scale, rv[i].y * scale,
                                   rv[i].z * scale, rv[i].w * scale);
        } else {
            float inv = 1.0f / cr[95 + seg];
            const float* src = cr + (seg - 1) * 32;
#pragma unroll
            for (int i = 0; i < 8; ++i)
                o[seg * 8 + i] = make_float4(src[4 * i + 0] * inv, src[4 * i + 1] * inv,
                                             src[4 * i + 2] * inv, src[4 * i + 3] * inv);
        }
    }
}

// ---------------- launch ----------------
extern "C" void kernel_launch(void* const* d_in, const int* in_sizes, int n_in,
                              void* d_out, int out_size) {
    (void)in_sizes; (void)n_in; (void)out_size;
    const int*   x    = (const int*)d_in[0];
    const float* rate = (const float*)d_in[1];
    const float* Wg   = (const float*)d_in[2];
    const float* Wd   = (const float*)d_in[3];
    const float* Wa   = (const float*)d_in[4];
    float*       out  = (float*)d_out;

    prep_w_kernel<<<(NW * KPAD + 255) / 256, 256>>>(Wg, Wd, Wa);

    cudaFuncSetAttribute(mli_main_kernel,
                         cudaFuncAttributeMaxDynamicSharedMemorySize, SMEM_DYN);
    mli_main_kernel<<<BROWS / MT, 256, SMEM_DYN>>>(x, rate, out);
}

// round 15
// speedup vs baseline: 1.5996x; 1.0538x over previous
#include <cuda_runtime.h>
#include <cuda_fp16.h>
#include <cstdint>
#include <cstddef>

#define XROW 10242
#define BROWS 16384
#define KT 64
#define NT 161                     // ceil(10242/64)
#define KPAD (NT * KT)             // 10304
#define NW 112                     // 96 emb cols + 3 count cols + pad
#define MT 64
#define ASTRIDE 144                // 64 halves (128B) + 16B pad -> row stride 36 banks == 4 mod 32
#define BSTRIDE 144
#define A_BYTES (MT * ASTRIDE)     // 9216
#define B_BYTES (NW * BSTRIDE)     // 16128
#define CSTRIDE 113
#define SMEM_DYN (2 * A_BYTES + 3 * B_BYTES + 1024)   // 67840 (C 64*113*4=28928 overlaid)

__device__ __half g_Wh[NW * KPAD]; // packed block-structured fp16 weights (~2.3 MB)

// ---------------- helpers ----------------
__device__ __forceinline__ uint32_t smem_u32(const void* p) {
    uint32_t a;
    asm("{ .reg .u64 t; cvta.to.shared.u64 t, %1; cvt.u32.u64 %0, t; }" : "=r"(a) : "l"(p));
    return a;
}
__device__ __forceinline__ void cp16(uint32_t dst, const void* src) {
    asm volatile("cp.async.cg.shared.global [%0], [%1], 16;" :: "r"(dst), "l"(src) : "memory");
}
__device__ __forceinline__ int2 ldcs64(const int* p) {
    int2 v;
    asm volatile("ld.global.cs.v2.s32 {%0,%1}, [%2];" : "=r"(v.x), "=r"(v.y) : "l"(p));
    return v;
}
__device__ __forceinline__ void ldsm4(uint32_t* r, uint32_t a) {
    asm volatile("ldmatrix.sync.aligned.m8n8.x4.shared.b16 {%0,%1,%2,%3}, [%4];"
                 : "=r"(r[0]), "=r"(r[1]), "=r"(r[2]), "=r"(r[3]) : "r"(a));
}
__device__ __forceinline__ void ldsm2(uint32_t* r, uint32_t a) {
    asm volatile("ldmatrix.sync.aligned.m8n8.x2.shared.b16 {%0,%1}, [%2];"
                 : "=r"(r[0]), "=r"(r[1]) : "r"(a));
}
__device__ __forceinline__ void mma16816(float* c, const uint32_t* a, uint32_t b0, uint32_t b1) {
    asm volatile(
        "mma.sync.aligned.m16n8k16.row.col.f32.f16.f16.f32 "
        "{%0,%1,%2,%3}, {%4,%5,%6,%7}, {%8,%9}, {%0,%1,%2,%3};"
        : "+f"(c[0]), "+f"(c[1]), "+f"(c[2]), "+f"(c[3])
        : "r"(a[0]), "r"(a[1]), "r"(a[2]), "r"(a[3]), "r"(b0), "r"(b1));
}

// ---------------- prep: pack W into [NW][KPAD] fp16 ----------------
// k=0: rate idx (zero row); [1,26): genre; [26,2212): director; [2212,10242): actor;
// [10242,KPAD): zero pad. Rows 96/97/98 = count indicator rows (1.0) per segment.
__global__ void prep_w_kernel(const float* __restrict__ Wg,
                              const float* __restrict__ Wd,
                              const float* __restrict__ Wa) {
    int idx = blockIdx.x * blockDim.x + threadIdx.x;
    if (idx >= NW * KPAD) return;
    int n = idx / KPAD;
    int k = idx - n * KPAD;
    float v = 0.0f;
    if (k >= 1 && k < 26) {
        if (n < 32)       v = Wg[n * 25 + (k - 1)];
        else if (n == 96) v = 1.0f;
    } else if (k >= 26 && k < 2212) {
        if (n >= 32 && n < 64) v = Wd[(n - 32) * 2186 + (k - 26)];
        else if (n == 97)      v = 1.0f;
    } else if (k >= 2212 && k < 10242) {
        if (n >= 64 && n < 96) v = Wa[(n - 64) * 8030 + (k - 2212)];
        else if (n == 98)      v = 1.0f;
    }
    g_Wh[idx] = __float2half_rn(v);
}

// ---------------- main kernel ----------------
__global__ void __launch_bounds__(256, 2)
mli_main_kernel(const int* __restrict__ x,
                const float* __restrict__ rate_table,
                float* __restrict__ out) {
    extern __shared__ char smem_raw[];
    const int tid  = threadIdx.x;
    const int wid  = tid >> 5;
    const int lane = tid & 31;
    const int gid  = lane >> 2;
    const int tid4 = lane & 3;
    const int wm   = wid >> 1;         // 0..3 : 16-row M slice
    const int wn   = wid & 1;          // 0..1 : 56-col N slice
    const int m_base = blockIdx.x * MT;

    uint32_t sbase = smem_u32(smem_raw);
    uint32_t tb = (sbase + 1023u) & ~1023u;
    const uint32_t Abuf[2] = { tb, tb + A_BYTES };
    const uint32_t Bbuf[3] = { tb + 2u * A_BYTES,
                               tb + 2u * A_BYTES + B_BYTES,
                               tb + 2u * A_BYTES + 2u * B_BYTES };

    // A staging: warp w handles rows w, w+8, ..., w+56; lane l loads int2 at col 2l.
    // LDG: 256B warp-contiguous. STS: bank (36*row + lane) % 32 -> conflict-free.
    const int* xbase = x + (size_t)(m_base + wid) * XROW + 2 * lane;
    const uint32_t a_dst = (uint32_t)(wid * ASTRIDE + lane * 4);

    int2 areg[8];
    auto load_a = [&](int k0, bool tail) {
        if (!tail) {
#pragma unroll
            for (int p = 0; p < 8; ++p)
                areg[p] = ldcs64(xbase + (size_t)p * 8 * XROW + k0);
        } else {
            int c0 = k0 + 2 * lane;
#pragma unroll
            for (int p = 0; p < 8; ++p) {
                const int* src = xbase + (size_t)p * 8 * XROW + k0;
                int v0 = (c0     < XROW) ? src[0] : 0;
                int v1 = (c0 + 1 < XROW) ? src[1] : 0;
                areg[p] = make_int2(v0, v1);
            }
        }
    };
    auto sts_a = [&](int buf) {
#pragma unroll
        for (int p = 0; p < 8; ++p) {
            __half2 hh = __floats2half2_rn((float)areg[p].x, (float)areg[p].y);
            asm volatile("st.shared.b32 [%0], %1;"
                         :: "r"(Abuf[buf] + a_dst + (uint32_t)(p * 8 * ASTRIDE)),
                            "r"(*reinterpret_cast<uint32_t*>(&hh)) : "memory");
        }
    };
    auto cp_b = [&](int k0, int buf) {
#pragma unroll
        for (int i = 0; i < 4; ++i) {
            int c = tid + i * 256;
            if (c < 896) {                       // 112 rows x 8 chunks of 16B
                int n = c >> 3, ch = c & 7;
                cp16(Bbuf[buf] + (uint32_t)(n * BSTRIDE + ch * 16),
                     g_Wh + (size_t)n * KPAD + k0 + ch * 8);
            }
        }
        asm volatile("cp.async.commit_group;" ::: "memory");
    };

    // ldmatrix lane-address offsets (byte offsets within a tile buffer)
    const uint32_t a_off =
        (uint32_t)((wm * 16 + ((lane >> 3) & 1) * 8 + (lane & 7)) * ASTRIDE
                   + (lane >> 4) * 16);
    uint32_t b_off[3];
#pragma unroll
    for (int jp = 0; jp < 3; ++jp)
        b_off[jp] = (uint32_t)((wn * 56 + jp * 16 + (lane >> 4) * 8 + (lane & 7)) * BSTRIDE
                               + ((lane >> 3) & 1) * 16);
    const uint32_t b_off2 =
        (uint32_t)((wn * 56 + 48 + (lane & 7)) * BSTRIDE + ((lane >> 3) & 1) * 16);

    float acc[7][4];
#pragma unroll
    for (int j = 0; j < 7; ++j)
#pragma unroll
        for (int q = 0; q < 4; ++q) acc[j][q] = 0.0f;

    // ---- prologue: stage tiles 0 and 1 ----
    load_a(0, false);
    cp_b(0, 0);                            // group for tile 0
    sts_a(0);                              // no prior readers -> no barrier needed
    load_a(KT, false);                     // A regs for tile 1
    cp_b(KT, 1);                           // group for tile 1

    // Pipeline invariant at iter t entry: groups committed for tiles <= t+1,
    // A regs hold tile t+1, Abuf[t&1] holds tile t.
    for (int t = 0; t < NT; ++t) {
        if (t + 1 < NT) {
            asm volatile("cp.async.wait_group 1;" ::: "memory");   // tile t's B done
        } else {
            asm volatile("cp.async.wait_group 0;" ::: "memory");
        }
        __syncthreads();   // all threads past compute(t-1); tile-t A/B visible

        // safe now: previous readers of these buffers are >= 1 barrier behind
        if (t + 1 < NT) sts_a((t + 1) & 1);
        if (t + 2 < NT) {
            load_a((t + 2) * KT, (t + 2) == NT - 1);
            cp_b((t + 2) * KT, (t + 2) % 3);
        }

        const uint32_t Ab = Abuf[t & 1], Bb = Bbuf[t % 3];
#pragma unroll
        for (int ks = 0; ks < 4; ++ks) {
            uint32_t afr[4];
            ldsm4(afr, Ab + a_off + ks * 32);
            uint32_t bfr[7][2];
#pragma unroll
            for (int jp = 0; jp < 3; ++jp) {
                uint32_t t4[4];
                ldsm4(t4, Bb + b_off[jp] + ks * 32);
                bfr[2 * jp][0] = t4[0]; bfr[2 * jp][1] = t4[1];
                bfr[2 * jp + 1][0] = t4[2]; bfr[2 * jp + 1][1] = t4[3];
            }
            ldsm2(bfr[6], Bb + b_off2 + ks * 32);
#pragma unroll
            for (int j = 0; j < 7; ++j)
                mma16816(acc[j], afr, bfr[j][0], bfr[j][1]);
        }
    }
    __syncthreads();   // protect C overlay of tile buffers

    // ---------------- epilogue ----------------
    float* Cs = (float*)(smem_raw + (tb - sbase));
    {
        int r0 = wm * 16 + gid;
#pragma unroll
        for (int j = 0; j < 7; ++j) {
            int c0 = wn * 56 + j * 8 + tid4 * 2;
            Cs[r0 * CSTRIDE + c0]           = acc[j][0];
            Cs[r0 * CSTRIDE + c0 + 1]       = acc[j][1];
            Cs[(r0 + 8) * CSTRIDE + c0]     = acc[j][2];
            Cs[(r0 + 8) * CSTRIDE + c0 + 1] = acc[j][3];
        }
    }
    __syncthreads();

    {
        const int row = tid >> 2;          // 0..63
        const int seg = tid & 3;           // 0: rate, 1: genre, 2: director, 3: actor
        const int rg  = m_base + row;
        const float* cr = Cs + row * CSTRIDE;
        float4* o = (float4*)(out + (size_t)rg * 128);

        if (seg == 0) {
            int ridx = x[(size_t)rg * XROW];
            const float4* rt = (const float4*)(rate_table + ridx * 32);
            float4 rv[8];
            float sq = 0.0f;
#pragma unroll
            for (int i = 0; i < 8; ++i) {
                rv[i] = rt[i];
                sq += rv[i].x * rv[i].x + rv[i].y * rv[i].y
                    + rv[i].z * rv[i].z + rv[i].w * rv[i].w;
            }
            float norm = sqrtf(sq);
            float scale = (norm > 1.0f) ? (1.0f / (norm + 1e-7f)) : 1.0f;
#pragma unroll
            for (int i = 0; i < 8; ++i)
                o[i] = make_float4(rv[i].x * scale, rv[i].y * scale,
                                   rv[i].z * scale, rv[i].w * scale);
        } else {
            float inv = 1.0f / cr[95 + seg];
            const float* src = cr + (seg - 1) * 32;
#pragma unroll
            for (int i = 0; i < 8; ++i)
                o[seg * 8 + i] = make_float4(src[4 * i + 0] * inv, src[4 * i + 1] * inv,
                                             src[4 * i + 2] * inv, src[4 * i + 3] * inv);
        }
    }
}

// ---------------- launch ----------------
extern "C" void kernel_launch(void* const* d_in, const int* in_sizes, int n_in,
                              void* d_out, int out_size) {
    (void)in_sizes; (void)n_in; (void)out_size;
    const int*   x    = (const int*)d_in[0];
    const float* rate = (const float*)d_in[1];
    const float* Wg   = (const float*)d_in[2];
    const float* Wd   = (const float*)d_in[3];
    const float* Wa   = (const float*)d_in[4];
    float*       out  = (float*)d_out;

    prep_w_kernel<<<(NW * KPAD + 255) / 256, 256>>>(Wg, Wd, Wa);

    cudaFuncSetAttribute(mli_main_kernel,
                         cudaFuncAttributeMaxDynamicSharedMemorySize, SMEM_DYN);
    mli_main_kernel<<<BROWS / MT, 256, SMEM_DYN>>>(x, rate, out);
}